// round 7
// baseline (speedup 1.0000x reference)
#include <cuda_runtime.h>

// Problem constants
#define BB 64
#define GG 1024
#define DD 256
#define LL 2
#define FF 1024
#define NEGV (-30.0f)

// ---------------------------------------------------------------------------
// Scratch (device globals — no allocation allowed in kernel_launch)
// ---------------------------------------------------------------------------
__device__ float g_q    [(size_t)BB * GG * DD];   // 64 MB
__device__ float g_k    [(size_t)BB * GG * DD];   // 64 MB
__device__ float g_v    [(size_t)BB * GG * DD];   // 64 MB
__device__ float g_heads[(size_t)BB * GG * DD];   // 64 MB
__device__ float g_h    [(size_t)BB * GG * DD];   // 64 MB
__device__ float g_c    [(size_t)BB * GG * GG];   // 256 MB (attention scores)
__device__ float g_t    [(size_t)BB * GG * FF];   // 256 MB (FFN hidden)

// ---------------------------------------------------------------------------
// Tiled SGEMM: C[b] = epilogue( alpha * A[b] @ op(B[b]) )
//   TRANS_B=false: B is [K,N] row-major (NN)
//   TRANS_B=true : B is [N,K] row-major (NT, i.e. A @ B^T)
// Epilogue: + bias[n] (if bias) + res[b][m,n] (if res), optional ReLU.
// Tile: BM=BN=128, BK=16, 256 threads, 8x8 microtile per thread.
// REQUIRES: M % 128 == 0, N % 128 == 0, K % 16 == 0 (true for all our shapes).
// ---------------------------------------------------------------------------
template <bool TRANS_B, bool RELU>
__global__ void __launch_bounds__(256, 2)
sgemm_kernel(const float* __restrict__ A, const float* __restrict__ Bm,
             const float* __restrict__ bias, const float* __restrict__ res,
             float* __restrict__ C,
             int M, int N, int K,
             long sA, long sB, long sC, long sRes,
             float alpha)
{
    const int tid = threadIdx.x;
    const int ty  = tid >> 4;   // 0..15  (M direction)
    const int tx  = tid & 15;   // 0..15  (N direction)

    const long bz = blockIdx.z;
    A  += bz * sA;
    Bm += bz * sB;
    C  += bz * sC;
    const float* resp = res ? (res + bz * sRes) : (const float*)0;

    const int m0 = blockIdx.y * 128;
    const int n0 = blockIdx.x * 128;

    __shared__ float As[16][128];
    __shared__ float Bs[16][128];

    float acc[8][8];
#pragma unroll
    for (int i = 0; i < 8; i++)
#pragma unroll
        for (int j = 0; j < 8; j++) acc[i][j] = 0.0f;

    for (int k0 = 0; k0 < K; k0 += 16) {
        // ---- load A tile (transposed into As[k][m]) ----
#pragma unroll
        for (int it = 0; it < 2; it++) {
            int lin = tid + it * 256;        // 0..511
            int row = lin >> 2;              // 0..127
            int kc  = (lin & 3) * 4;         // 0,4,8,12
            float4 va = *(const float4*)(A + (long)(m0 + row) * K + k0 + kc);
            As[kc + 0][row] = va.x;
            As[kc + 1][row] = va.y;
            As[kc + 2][row] = va.z;
            As[kc + 3][row] = va.w;
        }
        // ---- load B tile into Bs[k][n] ----
        if (TRANS_B) {
#pragma unroll
            for (int it = 0; it < 2; it++) {
                int lin = tid + it * 256;
                int n   = lin >> 2;          // 0..127
                int kc  = (lin & 3) * 4;
                float4 vb = *(const float4*)(Bm + (long)(n0 + n) * K + k0 + kc);
                Bs[kc + 0][n] = vb.x;
                Bs[kc + 1][n] = vb.y;
                Bs[kc + 2][n] = vb.z;
                Bs[kc + 3][n] = vb.w;
            }
        } else {
#pragma unroll
            for (int it = 0; it < 2; it++) {
                int lin = tid + it * 256;
                int kk  = lin >> 5;          // 0..15
                int nc  = (lin & 31) * 4;    // 0..124
                float4 vb = *(const float4*)(Bm + (long)(k0 + kk) * N + n0 + nc);
                *(float4*)&Bs[kk][nc] = vb;
            }
        }
        __syncthreads();

        // ---- 128x128x16 FMA block ----
#pragma unroll
        for (int k = 0; k < 16; k++) {
            float a[8], b[8];
            *(float4*)&a[0] = *(const float4*)&As[k][ty * 8];
            *(float4*)&a[4] = *(const float4*)&As[k][ty * 8 + 4];
            *(float4*)&b[0] = *(const float4*)&Bs[k][tx * 8];
            *(float4*)&b[4] = *(const float4*)&Bs[k][tx * 8 + 4];
#pragma unroll
            for (int i = 0; i < 8; i++)
#pragma unroll
                for (int j = 0; j < 8; j++)
                    acc[i][j] += a[i] * b[j];
        }
        __syncthreads();
    }

    // ---- epilogue ----
#pragma unroll
    for (int i = 0; i < 8; i++) {
        int m = m0 + ty * 8 + i;
#pragma unroll
        for (int j = 0; j < 8; j += 4) {
            int n = n0 + tx * 8 + j;
            float4 v;
            v.x = acc[i][j + 0] * alpha;
            v.y = acc[i][j + 1] * alpha;
            v.z = acc[i][j + 2] * alpha;
            v.w = acc[i][j + 3] * alpha;
            if (bias) {
                v.x += bias[n + 0];
                v.y += bias[n + 1];
                v.z += bias[n + 2];
                v.w += bias[n + 3];
            }
            if (resp) {
                float4 r = *(const float4*)(resp + (long)m * N + n);
                v.x += r.x; v.y += r.y; v.z += r.z; v.w += r.w;
            }
            if (RELU) {
                v.x = fmaxf(v.x, 0.0f);
                v.y = fmaxf(v.y, 0.0f);
                v.z = fmaxf(v.z, 0.0f);
                v.w = fmaxf(v.w, 0.0f);
            }
            *(float4*)(C + (long)m * N + n) = v;
        }
    }
}

// ---------------------------------------------------------------------------
// Masked softmax over the last dim of c[B,G,G] (in place).
// Matches reference exactly: masked -> -30 before softmax (still contributes
// exp(-30-max) to the denominator), masked -> 0 after softmax.
// One block per (q, b) row; 256 threads x 4 elements.
// ---------------------------------------------------------------------------
__global__ void __launch_bounds__(256)
softmax_mask_kernel(float* __restrict__ c, const int* __restrict__ mask)
{
    const int q = blockIdx.x;
    const int b = blockIdx.y;
    float* row = c + ((long)b * GG + q) * GG;
    const int* mrow = mask + b * GG;
    const int tid = threadIdx.x;

    float vals[4];
    int   msk[4];
    float mx = -1e30f;
#pragma unroll
    for (int t = 0; t < 4; t++) {
        int idx = tid + t * 256;
        int m = mrow[idx];
        float v = m ? NEGV : row[idx];
        vals[t] = v;
        msk[t]  = m;
        mx = fmaxf(mx, v);
    }

    __shared__ float red[8];
    // warp max
#pragma unroll
    for (int o = 16; o; o >>= 1) mx = fmaxf(mx, __shfl_xor_sync(0xffffffffu, mx, o));
    if ((tid & 31) == 0) red[tid >> 5] = mx;
    __syncthreads();
    {
        float v = red[tid & 7];
        mx = fmaxf(fmaxf(fmaxf(red[0], red[1]), fmaxf(red[2], red[3])),
                   fmaxf(fmaxf(red[4], red[5]), fmaxf(red[6], red[7])));
        (void)v;
    }
    __syncthreads();

    float e[4];
    float s = 0.0f;
#pragma unroll
    for (int t = 0; t < 4; t++) {
        e[t] = __expf(vals[t] - mx);
        s += e[t];
    }
    // warp sum
#pragma unroll
    for (int o = 16; o; o >>= 1) s += __shfl_xor_sync(0xffffffffu, s, o);
    if ((tid & 31) == 0) red[tid >> 5] = s;
    __syncthreads();
    float tot = red[0] + red[1] + red[2] + red[3]
              + red[4] + red[5] + red[6] + red[7];
    float inv = 1.0f / tot;

#pragma unroll
    for (int t = 0; t < 4; t++) {
        int idx = tid + t * 256;
        row[idx] = msk[t] ? 0.0f : e[t] * inv;
    }
}

// ---------------------------------------------------------------------------
// mean over G: mean[b,d] = (1/G) * sum_g h[b,g,d]. One block per batch,
// one thread per d (coalesced across threads). Deterministic (no atomics).
// ---------------------------------------------------------------------------
__global__ void __launch_bounds__(DD)
mean_kernel(const float* __restrict__ h, float* __restrict__ mean)
{
    const int b = blockIdx.x;
    const int d = threadIdx.x;
    const float* p = h + (long)b * GG * DD + d;
    float s = 0.0f;
#pragma unroll 8
    for (int g = 0; g < GG; g++)
        s += p[(long)g * DD];
    mean[b * DD + d] = s * (1.0f / (float)GG);
}

// ---------------------------------------------------------------------------
// Host launcher
// ---------------------------------------------------------------------------
extern "C" void kernel_launch(void* const* d_in, const int* in_sizes, int n_in,
                              void* d_out, int out_size)
{
    (void)in_sizes; (void)n_in; (void)out_size;

    const float* x    = (const float*)d_in[0];
    const int*   mask = (const int*)  d_in[1];
    const float* Wq   = (const float*)d_in[2];
    const float* Wk   = (const float*)d_in[3];
    const float* Wv   = (const float*)d_in[4];
    const float* Wo   = (const float*)d_in[5];
    const float* bo   = (const float*)d_in[6];
    const float* Wf1  = (const float*)d_in[7];
    const float* bf1  = (const float*)d_in[8];
    const float* Wf2  = (const float*)d_in[9];
    const float* bf2  = (const float*)d_in[10];
    float* out = (float*)d_out;

    float *q, *k, *v, *heads, *h, *c, *t;
    cudaGetSymbolAddress((void**)&q,     g_q);
    cudaGetSymbolAddress((void**)&k,     g_k);
    cudaGetSymbolAddress((void**)&v,     g_v);
    cudaGetSymbolAddress((void**)&heads, g_heads);
    cudaGetSymbolAddress((void**)&h,     g_h);
    cudaGetSymbolAddress((void**)&c,     g_c);
    cudaGetSymbolAddress((void**)&t,     g_t);

    const int  BG     = BB * GG;                 // 65536
    const long strQKV = (long)GG * DD;           // per-batch stride for q/k/v
    const long strC   = (long)GG * GG;           // per-batch stride for scores
    const dim3 blk(256);

    const dim3 gProj(DD / 128, BG / 128, 1);     // (2, 512)
    const dim3 gScores(GG / 128, GG / 128, BB);  // (8, 8, 64)
    const dim3 gHeads(DD / 128, GG / 128, BB);   // (2, 8, 64)
    const dim3 gFfn1(FF / 128, BG / 128, 1);     // (8, 512)

    const float* hin = x;
    for (int l = 0; l < LL; l++) {
        const float* wq = Wq  + (long)l * DD * DD;
        const float* wk = Wk  + (long)l * DD * DD;
        const float* wv = Wv  + (long)l * DD * DD;
        const float* wo = Wo  + (long)l * DD * DD;
        const float* w1 = Wf1 + (long)l * DD * FF;
        const float* w2 = Wf2 + (long)l * FF * DD;
        const float* b_o = bo  + l * DD;
        const float* b_1 = bf1 + l * FF;
        const float* b_2 = bf2 + l * DD;

        // Q, K, V projections: [BG,D] @ [D,D]
        sgemm_kernel<false, false><<<gProj, blk>>>(hin, wq, 0, 0, q,
            BG, DD, DD, 0, 0, 0, 0, 1.0f);
        sgemm_kernel<false, false><<<gProj, blk>>>(hin, wk, 0, 0, k,
            BG, DD, DD, 0, 0, 0, 0, 1.0f);
        sgemm_kernel<false, false><<<gProj, blk>>>(hin, wv, 0, 0, v,
            BG, DD, DD, 0, 0, 0, 0, 1.0f);

        // scores: c[b] = (1/16) * q[b] @ k[b]^T   (batched NT)
        sgemm_kernel<true, false><<<gScores, blk>>>(q, k, 0, 0, c,
            GG, GG, DD, strQKV, strQKV, strC, 0, 0.0625f);

        // masked softmax (in place on c)
        softmax_mask_kernel<<<dim3(GG, BB), 256>>>(c, mask);

        // heads: heads[b] = a[b] @ v[b]   (batched NN)
        sgemm_kernel<false, false><<<gHeads, blk>>>(c, v, 0, 0, heads,
            GG, DD, GG, strC, strQKV, strQKV, 0, 1.0f);

        // output projection + residual: h = hin + heads @ Wo + bo
        sgemm_kernel<false, false><<<gProj, blk>>>(heads, wo, b_o, hin, h,
            BG, DD, DD, 0, 0, 0, 0, 1.0f);

        // FFN up + ReLU: t = relu(h @ Wf1 + bf1)
        sgemm_kernel<false, true><<<gFfn1, blk>>>(h, w1, b_1, 0, t,
            BG, FF, DD, 0, 0, 0, 0, 1.0f);

        // FFN down + residual: h = h + t @ Wf2 + bf2
        float* hout = (l == LL - 1) ? out : h;
        sgemm_kernel<false, false><<<gProj, blk>>>(t, w2, b_2, h, hout,
            BG, DD, FF, 0, 0, 0, 0, 1.0f);

        hin = h;
    }

    // mean over the graph dim, appended after h in the output buffer
    mean_kernel<<<BB, DD>>>(out, out + (long)BB * GG * DD);
}

// round 8
// speedup vs baseline: 1.0014x; 1.0014x over previous
#include <cuda_runtime.h>

// Problem constants
#define BB 64
#define GG 1024
#define DD 256
#define LL 2
#define FF 1024
#define NEGV (-30.0f)

// ---------------------------------------------------------------------------
// Scratch (device globals — no allocation allowed in kernel_launch)
// ---------------------------------------------------------------------------
__device__ float g_q    [(size_t)BB * GG * DD];   // 64 MB
__device__ float g_k    [(size_t)BB * GG * DD];   // 64 MB
__device__ float g_v    [(size_t)BB * GG * DD];   // 64 MB
__device__ float g_heads[(size_t)BB * GG * DD];   // 64 MB
__device__ float g_h    [(size_t)BB * GG * DD];   // 64 MB
__device__ float g_c    [(size_t)BB * GG * GG];   // 256 MB (attention scores)
__device__ float g_t    [(size_t)BB * GG * FF];   // 256 MB (FFN hidden)

// ---------------------------------------------------------------------------
// Tiled SGEMM: C[b] = epilogue( alpha * A[b] @ op(B[b]) )
//   TRANS_B=false: B is [K,N] row-major (NN)
//   TRANS_B=true : B is [N,K] row-major (NT, i.e. A @ B^T)
// Epilogue: + bias[n] (if bias) + res[b][m,n] (if res), optional ReLU.
// Tile: BM=BN=128, BK=16, 256 threads, 8x8 microtile per thread.
// REQUIRES: M % 128 == 0, N % 128 == 0, K % 16 == 0 (true for all our shapes).
// ---------------------------------------------------------------------------
template <bool TRANS_B, bool RELU>
__global__ void __launch_bounds__(256, 2)
sgemm_kernel(const float* __restrict__ A, const float* __restrict__ Bm,
             const float* __restrict__ bias, const float* __restrict__ res,
             float* __restrict__ C,
             int M, int N, int K,
             long sA, long sB, long sC, long sRes,
             float alpha)
{
    const int tid = threadIdx.x;
    const int ty  = tid >> 4;   // 0..15  (M direction)
    const int tx  = tid & 15;   // 0..15  (N direction)

    const long bz = blockIdx.z;
    A  += bz * sA;
    Bm += bz * sB;
    C  += bz * sC;
    const float* resp = res ? (res + bz * sRes) : (const float*)0;

    const int m0 = blockIdx.y * 128;
    const int n0 = blockIdx.x * 128;

    __shared__ float As[16][128];
    __shared__ float Bs[16][128];

    float acc[8][8];
#pragma unroll
    for (int i = 0; i < 8; i++)
#pragma unroll
        for (int j = 0; j < 8; j++) acc[i][j] = 0.0f;

    for (int k0 = 0; k0 < K; k0 += 16) {
        // ---- load A tile (transposed into As[k][m]) ----
#pragma unroll
        for (int it = 0; it < 2; it++) {
            int lin = tid + it * 256;        // 0..511
            int row = lin >> 2;              // 0..127
            int kc  = (lin & 3) * 4;         // 0,4,8,12
            float4 va = *(const float4*)(A + (long)(m0 + row) * K + k0 + kc);
            As[kc + 0][row] = va.x;
            As[kc + 1][row] = va.y;
            As[kc + 2][row] = va.z;
            As[kc + 3][row] = va.w;
        }
        // ---- load B tile into Bs[k][n] ----
        if (TRANS_B) {
#pragma unroll
            for (int it = 0; it < 2; it++) {
                int lin = tid + it * 256;
                int n   = lin >> 2;          // 0..127
                int kc  = (lin & 3) * 4;
                float4 vb = *(const float4*)(Bm + (long)(n0 + n) * K + k0 + kc);
                Bs[kc + 0][n] = vb.x;
                Bs[kc + 1][n] = vb.y;
                Bs[kc + 2][n] = vb.z;
                Bs[kc + 3][n] = vb.w;
            }
        } else {
#pragma unroll
            for (int it = 0; it < 2; it++) {
                int lin = tid + it * 256;
                int kk  = lin >> 5;          // 0..15
                int nc  = (lin & 31) * 4;    // 0..124
                float4 vb = *(const float4*)(Bm + (long)(k0 + kk) * N + n0 + nc);
                *(float4*)&Bs[kk][nc] = vb;
            }
        }
        __syncthreads();

        // ---- 128x128x16 FMA block ----
#pragma unroll
        for (int k = 0; k < 16; k++) {
            float a[8], b[8];
            *(float4*)&a[0] = *(const float4*)&As[k][ty * 8];
            *(float4*)&a[4] = *(const float4*)&As[k][ty * 8 + 4];
            *(float4*)&b[0] = *(const float4*)&Bs[k][tx * 8];
            *(float4*)&b[4] = *(const float4*)&Bs[k][tx * 8 + 4];
#pragma unroll
            for (int i = 0; i < 8; i++)
#pragma unroll
                for (int j = 0; j < 8; j++)
                    acc[i][j] += a[i] * b[j];
        }
        __syncthreads();
    }

    // ---- epilogue ----
#pragma unroll
    for (int i = 0; i < 8; i++) {
        int m = m0 + ty * 8 + i;
#pragma unroll
        for (int j = 0; j < 8; j += 4) {
            int n = n0 + tx * 8 + j;
            float4 v;
            v.x = acc[i][j + 0] * alpha;
            v.y = acc[i][j + 1] * alpha;
            v.z = acc[i][j + 2] * alpha;
            v.w = acc[i][j + 3] * alpha;
            if (bias) {
                v.x += bias[n + 0];
                v.y += bias[n + 1];
                v.z += bias[n + 2];
                v.w += bias[n + 3];
            }
            if (resp) {
                float4 r = *(const float4*)(resp + (long)m * N + n);
                v.x += r.x; v.y += r.y; v.z += r.z; v.w += r.w;
            }
            if (RELU) {
                v.x = fmaxf(v.x, 0.0f);
                v.y = fmaxf(v.y, 0.0f);
                v.z = fmaxf(v.z, 0.0f);
                v.w = fmaxf(v.w, 0.0f);
            }
            *(float4*)(C + (long)m * N + n) = v;
        }
    }
}

// ---------------------------------------------------------------------------
// Masked softmax over the last dim of c[B,G,G] (in place).
// Matches reference exactly: masked -> -30 before softmax (still contributes
// exp(-30-max) to the denominator), masked -> 0 after softmax.
// One block per (q, b) row; 256 threads x 4 elements.
// ---------------------------------------------------------------------------
__global__ void __launch_bounds__(256)
softmax_mask_kernel(float* __restrict__ c, const int* __restrict__ mask)
{
    const int q = blockIdx.x;
    const int b = blockIdx.y;
    float* row = c + ((long)b * GG + q) * GG;
    const int* mrow = mask + b * GG;
    const int tid = threadIdx.x;

    float vals[4];
    int   msk[4];
    float mx = -1e30f;
#pragma unroll
    for (int t = 0; t < 4; t++) {
        int idx = tid + t * 256;
        int m = mrow[idx];
        float v = m ? NEGV : row[idx];
        vals[t] = v;
        msk[t]  = m;
        mx = fmaxf(mx, v);
    }

    __shared__ float red[8];
    // warp max
#pragma unroll
    for (int o = 16; o; o >>= 1) mx = fmaxf(mx, __shfl_xor_sync(0xffffffffu, mx, o));
    if ((tid & 31) == 0) red[tid >> 5] = mx;
    __syncthreads();
    {
        float v = red[tid & 7];
        mx = fmaxf(fmaxf(fmaxf(red[0], red[1]), fmaxf(red[2], red[3])),
                   fmaxf(fmaxf(red[4], red[5]), fmaxf(red[6], red[7])));
        (void)v;
    }
    __syncthreads();

    float e[4];
    float s = 0.0f;
#pragma unroll
    for (int t = 0; t < 4; t++) {
        e[t] = __expf(vals[t] - mx);
        s += e[t];
    }
    // warp sum
#pragma unroll
    for (int o = 16; o; o >>= 1) s += __shfl_xor_sync(0xffffffffu, s, o);
    if ((tid & 31) == 0) red[tid >> 5] = s;
    __syncthreads();
    float tot = red[0] + red[1] + red[2] + red[3]
              + red[4] + red[5] + red[6] + red[7];
    float inv = 1.0f / tot;

#pragma unroll
    for (int t = 0; t < 4; t++) {
        int idx = tid + t * 256;
        row[idx] = msk[t] ? 0.0f : e[t] * inv;
    }
}

// ---------------------------------------------------------------------------
// mean over G: mean[b,d] = (1/G) * sum_g h[b,g,d]. One block per batch,
// one thread per d (coalesced across threads). Deterministic (no atomics).
// ---------------------------------------------------------------------------
__global__ void __launch_bounds__(DD)
mean_kernel(const float* __restrict__ h, float* __restrict__ mean)
{
    const int b = blockIdx.x;
    const int d = threadIdx.x;
    const float* p = h + (long)b * GG * DD + d;
    float s = 0.0f;
#pragma unroll 8
    for (int g = 0; g < GG; g++)
        s += p[(long)g * DD];
    mean[b * DD + d] = s * (1.0f / (float)GG);
}

// ---------------------------------------------------------------------------
// Host launcher
// ---------------------------------------------------------------------------
extern "C" void kernel_launch(void* const* d_in, const int* in_sizes, int n_in,
                              void* d_out, int out_size)
{
    (void)in_sizes; (void)n_in; (void)out_size;

    const float* x    = (const float*)d_in[0];
    const int*   mask = (const int*)  d_in[1];
    const float* Wq   = (const float*)d_in[2];
    const float* Wk   = (const float*)d_in[3];
    const float* Wv   = (const float*)d_in[4];
    const float* Wo   = (const float*)d_in[5];
    const float* bo   = (const float*)d_in[6];
    const float* Wf1  = (const float*)d_in[7];
    const float* bf1  = (const float*)d_in[8];
    const float* Wf2  = (const float*)d_in[9];
    const float* bf2  = (const float*)d_in[10];
    float* out = (float*)d_out;

    float *q, *k, *v, *heads, *h, *c, *t;
    cudaGetSymbolAddress((void**)&q,     g_q);
    cudaGetSymbolAddress((void**)&k,     g_k);
    cudaGetSymbolAddress((void**)&v,     g_v);
    cudaGetSymbolAddress((void**)&heads, g_heads);
    cudaGetSymbolAddress((void**)&h,     g_h);
    cudaGetSymbolAddress((void**)&c,     g_c);
    cudaGetSymbolAddress((void**)&t,     g_t);

    const int  BG     = BB * GG;                 // 65536
    const long strQKV = (long)GG * DD;           // per-batch stride for q/k/v
    const long strC   = (long)GG * GG;           // per-batch stride for scores
    const dim3 blk(256);

    const dim3 gProj(DD / 128, BG / 128, 1);     // (2, 512)
    const dim3 gScores(GG / 128, GG / 128, BB);  // (8, 8, 64)
    const dim3 gHeads(DD / 128, GG / 128, BB);   // (2, 8, 64)
    const dim3 gFfn1(FF / 128, BG / 128, 1);     // (8, 512)

    const float* hin = x;
    for (int l = 0; l < LL; l++) {
        const float* wq = Wq  + (long)l * DD * DD;
        const float* wk = Wk  + (long)l * DD * DD;
        const float* wv = Wv  + (long)l * DD * DD;
        const float* wo = Wo  + (long)l * DD * DD;
        const float* w1 = Wf1 + (long)l * DD * FF;
        const float* w2 = Wf2 + (long)l * FF * DD;
        const float* b_o = bo  + l * DD;
        const float* b_1 = bf1 + l * FF;
        const float* b_2 = bf2 + l * DD;

        // Q, K, V projections: [BG,D] @ [D,D]
        sgemm_kernel<false, false><<<gProj, blk>>>(hin, wq, 0, 0, q,
            BG, DD, DD, 0, 0, 0, 0, 1.0f);
        sgemm_kernel<false, false><<<gProj, blk>>>(hin, wk, 0, 0, k,
            BG, DD, DD, 0, 0, 0, 0, 1.0f);
        sgemm_kernel<false, false><<<gProj, blk>>>(hin, wv, 0, 0, v,
            BG, DD, DD, 0, 0, 0, 0, 1.0f);

        // scores: c[b] = (1/16) * q[b] @ k[b]^T   (batched NT)
        sgemm_kernel<true, false><<<gScores, blk>>>(q, k, 0, 0, c,
            GG, GG, DD, strQKV, strQKV, strC, 0, 0.0625f);

        // masked softmax (in place on c)
        softmax_mask_kernel<<<dim3(GG, BB), 256>>>(c, mask);

        // heads: heads[b] = a[b] @ v[b]   (batched NN)
        sgemm_kernel<false, false><<<gHeads, blk>>>(c, v, 0, 0, heads,
            GG, DD, GG, strC, strQKV, strQKV, 0, 1.0f);

        // output projection + residual: h = hin + heads @ Wo + bo
        sgemm_kernel<false, false><<<gProj, blk>>>(heads, wo, b_o, hin, h,
            BG, DD, DD, 0, 0, 0, 0, 1.0f);

        // FFN up + ReLU: t = relu(h @ Wf1 + bf1)
        sgemm_kernel<false, true><<<gFfn1, blk>>>(h, w1, b_1, 0, t,
            BG, FF, DD, 0, 0, 0, 0, 1.0f);

        // FFN down + residual: h = h + t @ Wf2 + bf2
        float* hout = (l == LL - 1) ? out : h;
        sgemm_kernel<false, false><<<gProj, blk>>>(t, w2, b_2, h, hout,
            BG, DD, FF, 0, 0, 0, 0, 1.0f);

        hin = h;
    }

    // mean over the graph dim, appended after h in the output buffer
    mean_kernel<<<BB, DD>>>(out, out + (long)BB * GG * DD);
}

// round 9
// speedup vs baseline: 1.0019x; 1.0005x over previous
#include <cuda_runtime.h>

// Problem constants
#define BB 64
#define GG 1024
#define DD 256
#define LL 2
#define FF 1024
#define NEGV (-30.0f)

// ---------------------------------------------------------------------------
// Scratch (device globals — no allocation allowed in kernel_launch)
// ---------------------------------------------------------------------------
__device__ float g_q    [(size_t)BB * GG * DD];   // 64 MB
__device__ float g_k    [(size_t)BB * GG * DD];   // 64 MB
__device__ float g_v    [(size_t)BB * GG * DD];   // 64 MB
__device__ float g_heads[(size_t)BB * GG * DD];   // 64 MB
__device__ float g_h    [(size_t)BB * GG * DD];   // 64 MB
__device__ float g_c    [(size_t)BB * GG * GG];   // 256 MB (attention scores)
__device__ float g_t    [(size_t)BB * GG * FF];   // 256 MB (FFN hidden)

// ---------------------------------------------------------------------------
// Tiled SGEMM: C[b] = epilogue( alpha * A[b] @ op(B[b]) )
//   TRANS_B=false: B is [K,N] row-major (NN)
//   TRANS_B=true : B is [N,K] row-major (NT, i.e. A @ B^T)
// Epilogue: + bias[n] (if bias) + res[b][m,n] (if res), optional ReLU.
// Tile: BM=BN=128, BK=16, 256 threads, 8x8 microtile per thread.
// REQUIRES: M % 128 == 0, N % 128 == 0, K % 16 == 0 (true for all our shapes).
// ---------------------------------------------------------------------------
template <bool TRANS_B, bool RELU>
__global__ void __launch_bounds__(256, 2)
sgemm_kernel(const float* __restrict__ A, const float* __restrict__ Bm,
             const float* __restrict__ bias, const float* __restrict__ res,
             float* __restrict__ C,
             int M, int N, int K,
             long sA, long sB, long sC, long sRes,
             float alpha)
{
    const int tid = threadIdx.x;
    const int ty  = tid >> 4;   // 0..15  (M direction)
    const int tx  = tid & 15;   // 0..15  (N direction)

    const long bz = blockIdx.z;
    A  += bz * sA;
    Bm += bz * sB;
    C  += bz * sC;
    const float* resp = res ? (res + bz * sRes) : (const float*)0;

    const int m0 = blockIdx.y * 128;
    const int n0 = blockIdx.x * 128;

    __shared__ float As[16][128];
    __shared__ float Bs[16][128];

    float acc[8][8];
#pragma unroll
    for (int i = 0; i < 8; i++)
#pragma unroll
        for (int j = 0; j < 8; j++) acc[i][j] = 0.0f;

    for (int k0 = 0; k0 < K; k0 += 16) {
        // ---- load A tile (transposed into As[k][m]) ----
#pragma unroll
        for (int it = 0; it < 2; it++) {
            int lin = tid + it * 256;        // 0..511
            int row = lin >> 2;              // 0..127
            int kc  = (lin & 3) * 4;         // 0,4,8,12
            float4 va = *(const float4*)(A + (long)(m0 + row) * K + k0 + kc);
            As[kc + 0][row] = va.x;
            As[kc + 1][row] = va.y;
            As[kc + 2][row] = va.z;
            As[kc + 3][row] = va.w;
        }
        // ---- load B tile into Bs[k][n] ----
        if (TRANS_B) {
#pragma unroll
            for (int it = 0; it < 2; it++) {
                int lin = tid + it * 256;
                int n   = lin >> 2;          // 0..127
                int kc  = (lin & 3) * 4;
                float4 vb = *(const float4*)(Bm + (long)(n0 + n) * K + k0 + kc);
                Bs[kc + 0][n] = vb.x;
                Bs[kc + 1][n] = vb.y;
                Bs[kc + 2][n] = vb.z;
                Bs[kc + 3][n] = vb.w;
            }
        } else {
#pragma unroll
            for (int it = 0; it < 2; it++) {
                int lin = tid + it * 256;
                int kk  = lin >> 5;          // 0..15
                int nc  = (lin & 31) * 4;    // 0..124
                float4 vb = *(const float4*)(Bm + (long)(k0 + kk) * N + n0 + nc);
                *(float4*)&Bs[kk][nc] = vb;
            }
        }
        __syncthreads();

        // ---- 128x128x16 FMA block ----
#pragma unroll
        for (int k = 0; k < 16; k++) {
            float a[8], b[8];
            *(float4*)&a[0] = *(const float4*)&As[k][ty * 8];
            *(float4*)&a[4] = *(const float4*)&As[k][ty * 8 + 4];
            *(float4*)&b[0] = *(const float4*)&Bs[k][tx * 8];
            *(float4*)&b[4] = *(const float4*)&Bs[k][tx * 8 + 4];
#pragma unroll
            for (int i = 0; i < 8; i++)
#pragma unroll
                for (int j = 0; j < 8; j++)
                    acc[i][j] += a[i] * b[j];
        }
        __syncthreads();
    }

    // ---- epilogue ----
#pragma unroll
    for (int i = 0; i < 8; i++) {
        int m = m0 + ty * 8 + i;
#pragma unroll
        for (int j = 0; j < 8; j += 4) {
            int n = n0 + tx * 8 + j;
            float4 v;
            v.x = acc[i][j + 0] * alpha;
            v.y = acc[i][j + 1] * alpha;
            v.z = acc[i][j + 2] * alpha;
            v.w = acc[i][j + 3] * alpha;
            if (bias) {
                v.x += bias[n + 0];
                v.y += bias[n + 1];
                v.z += bias[n + 2];
                v.w += bias[n + 3];
            }
            if (resp) {
                float4 r = *(const float4*)(resp + (long)m * N + n);
                v.x += r.x; v.y += r.y; v.z += r.z; v.w += r.w;
            }
            if (RELU) {
                v.x = fmaxf(v.x, 0.0f);
                v.y = fmaxf(v.y, 0.0f);
                v.z = fmaxf(v.z, 0.0f);
                v.w = fmaxf(v.w, 0.0f);
            }
            *(float4*)(C + (long)m * N + n) = v;
        }
    }
}

// ---------------------------------------------------------------------------
// Masked softmax over the last dim of c[B,G,G] (in place).
// Matches reference exactly: masked -> -30 before softmax (still contributes
// exp(-30-max) to the denominator), masked -> 0 after softmax.
// One block per (q, b) row; 256 threads x 4 elements.
// ---------------------------------------------------------------------------
__global__ void __launch_bounds__(256)
softmax_mask_kernel(float* __restrict__ c, const int* __restrict__ mask)
{
    const int q = blockIdx.x;
    const int b = blockIdx.y;
    float* row = c + ((long)b * GG + q) * GG;
    const int* mrow = mask + b * GG;
    const int tid = threadIdx.x;

    float vals[4];
    int   msk[4];
    float mx = -1e30f;
#pragma unroll
    for (int t = 0; t < 4; t++) {
        int idx = tid + t * 256;
        int m = mrow[idx];
        float v = m ? NEGV : row[idx];
        vals[t] = v;
        msk[t]  = m;
        mx = fmaxf(mx, v);
    }

    __shared__ float red[8];
    // warp max
#pragma unroll
    for (int o = 16; o; o >>= 1) mx = fmaxf(mx, __shfl_xor_sync(0xffffffffu, mx, o));
    if ((tid & 31) == 0) red[tid >> 5] = mx;
    __syncthreads();
    {
        float v = red[tid & 7];
        mx = fmaxf(fmaxf(fmaxf(red[0], red[1]), fmaxf(red[2], red[3])),
                   fmaxf(fmaxf(red[4], red[5]), fmaxf(red[6], red[7])));
        (void)v;
    }
    __syncthreads();

    float e[4];
    float s = 0.0f;
#pragma unroll
    for (int t = 0; t < 4; t++) {
        e[t] = __expf(vals[t] - mx);
        s += e[t];
    }
    // warp sum
#pragma unroll
    for (int o = 16; o; o >>= 1) s += __shfl_xor_sync(0xffffffffu, s, o);
    if ((tid & 31) == 0) red[tid >> 5] = s;
    __syncthreads();
    float tot = red[0] + red[1] + red[2] + red[3]
              + red[4] + red[5] + red[6] + red[7];
    float inv = 1.0f / tot;

#pragma unroll
    for (int t = 0; t < 4; t++) {
        int idx = tid + t * 256;
        row[idx] = msk[t] ? 0.0f : e[t] * inv;
    }
}

// ---------------------------------------------------------------------------
// mean over G: mean[b,d] = (1/G) * sum_g h[b,g,d]. One block per batch,
// one thread per d (coalesced across threads). Deterministic (no atomics).
// ---------------------------------------------------------------------------
__global__ void __launch_bounds__(DD)
mean_kernel(const float* __restrict__ h, float* __restrict__ mean)
{
    const int b = blockIdx.x;
    const int d = threadIdx.x;
    const float* p = h + (long)b * GG * DD + d;
    float s = 0.0f;
#pragma unroll 8
    for (int g = 0; g < GG; g++)
        s += p[(long)g * DD];
    mean[b * DD + d] = s * (1.0f / (float)GG);
}

// ---------------------------------------------------------------------------
// Host launcher
// ---------------------------------------------------------------------------
extern "C" void kernel_launch(void* const* d_in, const int* in_sizes, int n_in,
                              void* d_out, int out_size)
{
    (void)in_sizes; (void)n_in; (void)out_size;

    const float* x    = (const float*)d_in[0];
    const int*   mask = (const int*)  d_in[1];
    const float* Wq   = (const float*)d_in[2];
    const float* Wk   = (const float*)d_in[3];
    const float* Wv   = (const float*)d_in[4];
    const float* Wo   = (const float*)d_in[5];
    const float* bo   = (const float*)d_in[6];
    const float* Wf1  = (const float*)d_in[7];
    const float* bf1  = (const float*)d_in[8];
    const float* Wf2  = (const float*)d_in[9];
    const float* bf2  = (const float*)d_in[10];
    float* out = (float*)d_out;

    float *q, *k, *v, *heads, *h, *c, *t;
    cudaGetSymbolAddress((void**)&q,     g_q);
    cudaGetSymbolAddress((void**)&k,     g_k);
    cudaGetSymbolAddress((void**)&v,     g_v);
    cudaGetSymbolAddress((void**)&heads, g_heads);
    cudaGetSymbolAddress((void**)&h,     g_h);
    cudaGetSymbolAddress((void**)&c,     g_c);
    cudaGetSymbolAddress((void**)&t,     g_t);

    const int  BG     = BB * GG;                 // 65536
    const long strQKV = (long)GG * DD;           // per-batch stride for q/k/v
    const long strC   = (long)GG * GG;           // per-batch stride for scores
    const dim3 blk(256);

    const dim3 gProj(DD / 128, BG / 128, 1);     // (2, 512)
    const dim3 gScores(GG / 128, GG / 128, BB);  // (8, 8, 64)
    const dim3 gHeads(DD / 128, GG / 128, BB);   // (2, 8, 64)
    const dim3 gFfn1(FF / 128, BG / 128, 1);     // (8, 512)

    const float* hin = x;
    for (int l = 0; l < LL; l++) {
        const float* wq = Wq  + (long)l * DD * DD;
        const float* wk = Wk  + (long)l * DD * DD;
        const float* wv = Wv  + (long)l * DD * DD;
        const float* wo = Wo  + (long)l * DD * DD;
        const float* w1 = Wf1 + (long)l * DD * FF;
        const float* w2 = Wf2 + (long)l * FF * DD;
        const float* b_o = bo  + l * DD;
        const float* b_1 = bf1 + l * FF;
        const float* b_2 = bf2 + l * DD;

        // Q, K, V projections: [BG,D] @ [D,D]
        sgemm_kernel<false, false><<<gProj, blk>>>(hin, wq, 0, 0, q,
            BG, DD, DD, 0, 0, 0, 0, 1.0f);
        sgemm_kernel<false, false><<<gProj, blk>>>(hin, wk, 0, 0, k,
            BG, DD, DD, 0, 0, 0, 0, 1.0f);
        sgemm_kernel<false, false><<<gProj, blk>>>(hin, wv, 0, 0, v,
            BG, DD, DD, 0, 0, 0, 0, 1.0f);

        // scores: c[b] = (1/16) * q[b] @ k[b]^T   (batched NT)
        sgemm_kernel<true, false><<<gScores, blk>>>(q, k, 0, 0, c,
            GG, GG, DD, strQKV, strQKV, strC, 0, 0.0625f);

        // masked softmax (in place on c)
        softmax_mask_kernel<<<dim3(GG, BB), 256>>>(c, mask);

        // heads: heads[b] = a[b] @ v[b]   (batched NN)
        sgemm_kernel<false, false><<<gHeads, blk>>>(c, v, 0, 0, heads,
            GG, DD, GG, strC, strQKV, strQKV, 0, 1.0f);

        // output projection + residual: h = hin + heads @ Wo + bo
        sgemm_kernel<false, false><<<gProj, blk>>>(heads, wo, b_o, hin, h,
            BG, DD, DD, 0, 0, 0, 0, 1.0f);

        // FFN up + ReLU: t = relu(h @ Wf1 + bf1)
        sgemm_kernel<false, true><<<gFfn1, blk>>>(h, w1, b_1, 0, t,
            BG, FF, DD, 0, 0, 0, 0, 1.0f);

        // FFN down + residual: h = h + t @ Wf2 + bf2
        float* hout = (l == LL - 1) ? out : h;
        sgemm_kernel<false, false><<<gProj, blk>>>(t, w2, b_2, h, hout,
            BG, DD, FF, 0, 0, 0, 0, 1.0f);

        hin = h;
    }

    // mean over the graph dim, appended after h in the output buffer
    mean_kernel<<<BB, DD>>>(out, out + (long)BB * GG * DD);
}